// round 3
// baseline (speedup 1.0000x reference)
#include <cuda_runtime.h>
#include <math.h>

// MMD loss: z is [8192, 256] fp32. SIGMA=1 -> gamma=0.5.
// term_a = mean_ij exp(-0.5 * max(sq_i + sq_j - 2*z_i.z_j, 0))
// term_b, term_c underflow fp32 but are computed faithfully.

#define NROWS 8192
#define DIM   256
#define BM    128
#define BN    128
#define BK    16
#define TM    8
#define TN    8
#define NTHREADS 256   // (BM/TM)*(BN/TN)

__device__ float  g_sq[NROWS];
__device__ double g_accum;

// ---------------------------------------------------------------------------
// Kernel 1: per-row squared norms, accumulated in the SAME order (ascending k,
// sequential fmaf chain) as the GEMM accumulator so that the diagonal
// dist_sq(i,i) = sq_i + sq_i - 2*acc_ii is bitwise zero.
// Also zeroes the global accumulator (single writer; consumers run later in
// stream order, so this is race-free and graph-replay-safe).
// ---------------------------------------------------------------------------
__global__ void sq_kernel(const float* __restrict__ z)
{
    int i = blockIdx.x * blockDim.x + threadIdx.x;
    if (i == 0 && blockIdx.x == 0) g_accum = 0.0;
    if (i < NROWS) {
        const float* row = z + (size_t)i * DIM;
        float s = 0.0f;
        #pragma unroll 8
        for (int k = 0; k < DIM; k++) {
            float v = row[k];
            s = fmaf(v, v, s);           // serial dependent chain, k ascending
        }
        g_sq[i] = s;
    }
}

// ---------------------------------------------------------------------------
// Kernel 2: symmetric tiled Gram + exp epilogue + block reduction.
// Grid 64x64; blocks with bj < bi exit immediately (upper triangle only).
// Off-diagonal tiles weighted x2; diagonal tiles keep i<j (x2), i==j (x1).
// ---------------------------------------------------------------------------
__global__ void __launch_bounds__(NTHREADS) mmd_kernel(const float* __restrict__ z)
{
    const int bi = blockIdx.y;
    const int bj = blockIdx.x;
    if (bj < bi) return;

    __shared__ float As[BK][BM];
    __shared__ float Bs[BK][BN];

    const int tid = threadIdx.x;
    const int tx  = tid & 15;    // 0..15 -> column group
    const int ty  = tid >> 4;    // 0..15 -> row group

    float acc[TM][TN];
    #pragma unroll
    for (int i = 0; i < TM; i++)
        #pragma unroll
        for (int j = 0; j < TN; j++)
            acc[i][j] = 0.0f;

    const float* Abase = z + (size_t)bi * BM * DIM;
    const float* Bbase = z + (size_t)bj * BM * DIM;

    for (int k0 = 0; k0 < DIM; k0 += BK) {
        // Load 128x16 A tile and B tile, k-major in smem.
        // 512 float4 per tile, 2 per thread.
        #pragma unroll
        for (int l = 0; l < 2; l++) {
            int idx = tid + l * NTHREADS;     // 0..511
            int m   = idx >> 2;               // 0..127 (row within tile)
            int kq  = (idx & 3) << 2;         // 0,4,8,12

            float4 a = *(const float4*)(Abase + (size_t)m * DIM + k0 + kq);
            As[kq + 0][m] = a.x;
            As[kq + 1][m] = a.y;
            As[kq + 2][m] = a.z;
            As[kq + 3][m] = a.w;

            float4 b = *(const float4*)(Bbase + (size_t)m * DIM + k0 + kq);
            Bs[kq + 0][m] = b.x;
            Bs[kq + 1][m] = b.y;
            Bs[kq + 2][m] = b.z;
            Bs[kq + 3][m] = b.w;
        }
        __syncthreads();

        #pragma unroll
        for (int k = 0; k < BK; k++) {
            float rm[TM], rn[TN];
            #pragma unroll
            for (int i = 0; i < TM; i++) rm[i] = As[k][ty * TM + i];
            #pragma unroll
            for (int j = 0; j < TN; j++) rn[j] = Bs[k][tx * TN + j];
            #pragma unroll
            for (int i = 0; i < TM; i++)
                #pragma unroll
                for (int j = 0; j < TN; j++)
                    acc[i][j] = fmaf(rm[i], rn[j], acc[i][j]);
        }
        __syncthreads();
    }

    // Epilogue: dist_sq -> exp -> weighted local sum
    const int  rowbase = bi * BM + ty * TM;
    const int  colbase = bj * BM + tx * TN;
    const bool diag    = (bi == bj);

    float local = 0.0f;
    #pragma unroll
    for (int i = 0; i < TM; i++) {
        const int   ig  = rowbase + i;
        const float sqi = g_sq[ig];
        #pragma unroll
        for (int j = 0; j < TN; j++) {
            const int jg = colbase + j;
            float w = 2.0f;
            if (diag) w = (ig < jg) ? 2.0f : ((ig == jg) ? 1.0f : 0.0f);
            float d = (sqi + g_sq[jg]) - 2.0f * acc[i][j];
            d = fmaxf(d, 0.0f);
            local += w * __expf(-0.5f * d);
        }
    }

    // Block reduction + one double atomic per block (2080 active blocks)
    __shared__ float red[NTHREADS];
    red[tid] = local;
    __syncthreads();
    #pragma unroll
    for (int s = NTHREADS / 2; s > 0; s >>= 1) {
        if (tid < s) red[tid] += red[tid + s];
        __syncthreads();
    }
    if (tid == 0) atomicAdd(&g_accum, (double)red[0]);
}

// ---------------------------------------------------------------------------
// Kernel 3: finalize. term_b/term_c computed faithfully (they underflow fp32
// exactly as in the reference).
// ---------------------------------------------------------------------------
__global__ void finalize_kernel(float* __restrict__ out)
{
    __shared__ float red[256];
    const int tid = threadIdx.x;

    float s = 0.0f;
    for (int i = tid; i < NROWS; i += 256)
        s += __expf(-0.25f * g_sq[i]);      // gamma/denom_b = 0.5/2 = 0.25
    red[tid] = s;
    __syncthreads();
    #pragma unroll
    for (int t = 128; t > 0; t >>= 1) {
        if (tid < t) red[tid] += red[tid + t];
        __syncthreads();
    }

    if (tid == 0) {
        const double n = (double)NROWS;
        double term_a  = g_accum / (n * n);
        double coeff_b = 1.0 / pow(2.0, 128.0);     // denom_b=2, d/2=128
        double term_b  = coeff_b * ((double)red[0] / n);
        double term_c  = 1.0 / pow(3.0, 128.0);     // (1+4*gamma)^(d/2)
        out[0] = (float)(term_a - 2.0 * term_b + term_c);
    }
}

// ---------------------------------------------------------------------------
extern "C" void kernel_launch(void* const* d_in, const int* in_sizes, int n_in,
                              void* d_out, int out_size)
{
    const float* z   = (const float*)d_in[0];
    float*       out = (float*)d_out;

    sq_kernel<<<(NROWS + 255) / 256, 256>>>(z);

    dim3 grid(NROWS / BN, NROWS / BM);   // 64 x 64; lower triangle exits early
    mmd_kernel<<<grid, NTHREADS>>>(z);

    finalize_kernel<<<1, 256>>>(out);
}

// round 8
// speedup vs baseline: 4.3089x; 4.3089x over previous
#include <cuda_runtime.h>
#include <cuda_bf16.h>
#include <stdint.h>
#include <cstdint>
#include <math.h>

// MMD loss on GB300 via warp-level bf16 mma.sync (base sm_103-legal path;
// tcgen05 is rejected by the harness's .target sm_103 PTX stage).
// z: [8192, 256] fp32. gamma = 0.5.

#define NROWS 8192
#define DIM   256
#define BM    128
#define BN    128
#define NTHREADS 256

// SMEM layout (bytes). Row stride in tiles: 256 bf16 = 512 B.
#define SM_A   0                    // 128 x 512 B = 65536
#define SM_B   65536                // 65536
#define SM_SQI 131072               // 128 floats
#define SM_SQJ (131072 + 512)       // 128 floats
#define SM_RED (131072 + 1024)      // 256 floats
#define SMEM_TOTAL (131072 + 2048)

__device__ __nv_bfloat16 g_zb[NROWS * DIM];
__device__ float  g_sq[NROWS];
__device__ double g_accum;

// ---------------------------------------------------------------------------
// helpers
// ---------------------------------------------------------------------------
__device__ __forceinline__ uint32_t smem_u32(const void* p) {
    uint32_t a;
    asm("{ .reg .u64 t; cvta.to.shared.u64 t, %1; cvt.u32.u64 %0, t; }"
        : "=r"(a) : "l"(p));
    return a;
}

__device__ __forceinline__ void cp16(uint32_t s, const void* g) {
    asm volatile("cp.async.cg.shared.global [%0], [%1], 16;"
                 :: "r"(s), "l"(g) : "memory");
}

__device__ __forceinline__ void ldsm4(uint32_t* r, uint32_t addr) {
    asm volatile("ldmatrix.sync.aligned.m8n8.x4.shared.b16 {%0,%1,%2,%3}, [%4];"
                 : "=r"(r[0]), "=r"(r[1]), "=r"(r[2]), "=r"(r[3])
                 : "r"(addr));
}

__device__ __forceinline__ void mma16816(float* d, const uint32_t* a,
                                         const uint32_t* b) {
    asm volatile(
        "mma.sync.aligned.m16n8k16.row.col.f32.bf16.bf16.f32 "
        "{%0,%1,%2,%3}, {%4,%5,%6,%7}, {%8,%9}, {%0,%1,%2,%3};"
        : "+f"(d[0]), "+f"(d[1]), "+f"(d[2]), "+f"(d[3])
        : "r"(a[0]), "r"(a[1]), "r"(a[2]), "r"(a[3]),
          "r"(b[0]), "r"(b[1]));
}

// swizzled byte offset inside a tile: row-major [128][256 bf16], 16B chunks
// XORed with (row & 7) -> ldmatrix conflict-free.
__device__ __forceinline__ uint32_t sw_off(int row, int kc16) {
    return (uint32_t)row * 512u + (uint32_t)((kc16 ^ (row & 7)) << 4);
}

// ---------------------------------------------------------------------------
// Kernel 1: fp32 -> bf16 convert + per-row squared norms. One warp per row.
// ---------------------------------------------------------------------------
__global__ void __launch_bounds__(256) prep_kernel(const float* __restrict__ z)
{
    if (blockIdx.x == 0 && threadIdx.x == 0) g_accum = 0.0;

    const int w    = (blockIdx.x * blockDim.x + threadIdx.x) >> 5;  // row
    const int lane = threadIdx.x & 31;
    if (w >= NROWS) return;

    const float4* row = (const float4*)(z + (size_t)w * DIM);
    float4 a = row[lane * 2];
    float4 b = row[lane * 2 + 1];

    float s = a.x*a.x + a.y*a.y + a.z*a.z + a.w*a.w
            + b.x*b.x + b.y*b.y + b.z*b.z + b.w*b.w;

    __nv_bfloat162 p0 = __floats2bfloat162_rn(a.x, a.y);
    __nv_bfloat162 p1 = __floats2bfloat162_rn(a.z, a.w);
    __nv_bfloat162 p2 = __floats2bfloat162_rn(b.x, b.y);
    __nv_bfloat162 p3 = __floats2bfloat162_rn(b.z, b.w);
    uint4 pk;
    pk.x = *(uint32_t*)&p0;  pk.y = *(uint32_t*)&p1;
    pk.z = *(uint32_t*)&p2;  pk.w = *(uint32_t*)&p3;
    *(uint4*)(g_zb + (size_t)w * DIM + lane * 8) = pk;

    #pragma unroll
    for (int o = 16; o > 0; o >>= 1)
        s += __shfl_xor_sync(0xFFFFFFFFu, s, o);
    if (lane == 0) g_sq[w] = s;
}

// ---------------------------------------------------------------------------
// Kernel 2: symmetric tiled Gram via mma.sync bf16 + exp epilogue.
// Grid 64x64; blocks with bj < bi exit. 8 warps, warp tile 32x64.
// ---------------------------------------------------------------------------
__global__ void __launch_bounds__(NTHREADS) gram_kernel()
{
    const int bi = blockIdx.y;
    const int bj = blockIdx.x;
    if (bj < bi) return;

    extern __shared__ char smem[];
    const uint32_t sb  = smem_u32(smem);
    const int tid  = threadIdx.x;
    const int wid  = tid >> 5;
    const int lane = tid & 31;

    // ---- async-load A (rows bi*128..) and B (rows bj*128..), swizzled ----
    const __nv_bfloat16* Ab = g_zb + (size_t)bi * BM * DIM;
    const __nv_bfloat16* Bb = g_zb + (size_t)bj * BN * DIM;

    #pragma unroll
    for (int t = 0; t < 16; t++) {
        int idx = tid + t * NTHREADS;      // 0..4095
        int row = idx >> 5;                // 0..127
        int kc  = idx & 31;                // 16B chunk (8 bf16)
        uint32_t so = sw_off(row, kc);
        cp16(sb + SM_A + so, Ab + row * DIM + kc * 8);
        cp16(sb + SM_B + so, Bb + row * DIM + kc * 8);
    }
    asm volatile("cp.async.commit_group;" ::: "memory");

    // stage sq values while loads fly
    float* sqi_s = (float*)(smem + SM_SQI);
    float* sqj_s = (float*)(smem + SM_SQJ);
    if (tid < 128) sqi_s[tid] = g_sq[bi * BM + tid];
    else           sqj_s[tid - 128] = g_sq[bj * BN + (tid - 128)];

    asm volatile("cp.async.wait_group 0;" ::: "memory");
    __syncthreads();

    // ---- mma mainloop ----
    const int wm = (wid & 3) * 32;     // warp row base
    const int wn = (wid >> 2) * 64;    // warp col base

    float acc[2][8][4];
    #pragma unroll
    for (int mi = 0; mi < 2; mi++)
        #pragma unroll
        for (int ni = 0; ni < 8; ni++)
            #pragma unroll
            for (int r = 0; r < 4; r++)
                acc[mi][ni][r] = 0.0f;

    #pragma unroll 4
    for (int k0 = 0; k0 < DIM; k0 += 16) {
        const int kc0 = k0 >> 3;       // 16B-chunk index of k0

        uint32_t a[2][4];
        #pragma unroll
        for (int mi = 0; mi < 2; mi++) {
            int row = wm + mi * 16 + (lane & 15);
            int kc  = kc0 + (lane >> 4);
            ldsm4(a[mi], sb + SM_A + sw_off(row, kc));
        }

        uint32_t b[4][4];
        #pragma unroll
        for (int nq = 0; nq < 4; nq++) {
            int row = wn + nq * 16 + (lane & 7) + ((lane >> 4) << 3);
            int kc  = kc0 + ((lane >> 3) & 1);
            ldsm4(b[nq], sb + SM_B + sw_off(row, kc));
        }

        #pragma unroll
        for (int mi = 0; mi < 2; mi++)
            #pragma unroll
            for (int nq = 0; nq < 4; nq++) {
                mma16816(acc[mi][nq * 2],     a[mi], &b[nq][0]);
                mma16816(acc[mi][nq * 2 + 1], a[mi], &b[nq][2]);
            }
    }

    // ---- epilogue: dist -> exp -> weighted sum ----
    const bool diag = (bi == bj);
    const int t4 = lane >> 2;          // 0..7
    const int t2 = (lane & 3) << 1;    // 0,2,4,6

    float local = 0.0f;
    #pragma unroll
    for (int mi = 0; mi < 2; mi++) {
        #pragma unroll
        for (int ni = 0; ni < 8; ni++) {
            #pragma unroll
            for (int r = 0; r < 4; r++) {
                int il = wm + mi * 16 + t4 + ((r >> 1) << 3);
                int jl = wn + ni * 8 + t2 + (r & 1);
                float d = fmaf(-2.0f, acc[mi][ni][r], sqi_s[il] + sqj_s[jl]);
                // off-diagonal d ~ 512 -> exp underflows to 0.0f exactly; skip
                if (d < 176.0f) {
                    if (!diag) {
                        local += 2.0f * __expf(-0.5f * d);
                    } else {
                        if (il == jl)      local += 1.0f;   // exact diagonal
                        else if (jl > il)  local += 2.0f * __expf(-0.5f * d);
                    }
                }
            }
        }
    }

    // block reduce + one double atomic
    float* red = (float*)(smem + SM_RED);
    red[tid] = local;
    __syncthreads();
    #pragma unroll
    for (int s = NTHREADS / 2; s > 0; s >>= 1) {
        if (tid < s) red[tid] += red[tid + s];
        __syncthreads();
    }
    if (tid == 0) atomicAdd(&g_accum, (double)red[0]);
}

// ---------------------------------------------------------------------------
// Kernel 3: finalize (term_b / term_c underflow fp32, computed faithfully)
// ---------------------------------------------------------------------------
__global__ void finalize_kernel(float* __restrict__ out)
{
    __shared__ float fred[256];
    const int tid = threadIdx.x;

    float s = 0.0f;
    for (int idx = tid; idx < NROWS; idx += 256)
        s += __expf(-0.25f * g_sq[idx]);      // gamma/denom_b = 0.25
    fred[tid] = s;
    __syncthreads();
    #pragma unroll
    for (int t = 128; t > 0; t >>= 1) {
        if (tid < t) fred[tid] += fred[tid + t];
        __syncthreads();
    }

    if (tid == 0) {
        const double n = (double)NROWS;
        double term_a  = g_accum / (n * n);
        double coeff_b = 1.0 / pow(2.0, 128.0);   // denom_b=2, d/2=128
        double term_b  = coeff_b * ((double)fred[0] / n);
        double term_c  = 1.0 / pow(3.0, 128.0);   // (1+4*gamma)^(d/2)
        out[0] = (float)(term_a - 2.0 * term_b + term_c);
    }
}

// ---------------------------------------------------------------------------
extern "C" void kernel_launch(void* const* d_in, const int* in_sizes, int n_in,
                              void* d_out, int out_size)
{
    const float* z   = (const float*)d_in[0];
    float*       out = (float*)d_out;

    cudaFuncSetAttribute(gram_kernel,
                         cudaFuncAttributeMaxDynamicSharedMemorySize, SMEM_TOTAL);

    prep_kernel<<<NROWS / 8, 256>>>(z);                 // 8 warps/block

    dim3 grid(NROWS / BN, NROWS / BM);                  // 64 x 64
    gram_kernel<<<grid, NTHREADS, SMEM_TOTAL>>>();

    finalize_kernel<<<1, 256>>>(out);
}

// round 9
// speedup vs baseline: 4.8014x; 1.1143x over previous
#include <cuda_runtime.h>
#include <cuda_bf16.h>
#include <stdint.h>
#include <cstdint>
#include <math.h>

// MMD loss, persistent-block bf16 mma.sync Gram with double-buffered B tiles.
// z: [8192, 256] fp32. gamma = 0.5.

#define NROWS 8192
#define DIM   256
#define BM    128
#define BN    128
#define NTHREADS 256
#define NBLK   152            // GB300: 152 SMs, occ=1 (194 KB smem)
#define NTILES 2080           // upper-triangle 64x64 tile grid
#define TPB    13             // 2080 = 152*13 + 104
#define TREM   104

// SMEM layout (bytes). Tile row stride: 256 bf16 = 512 B.
#define SM_A    0                      // 64 KB
#define SM_B0   65536                  // 64 KB
#define SM_B1   131072                 // 64 KB
#define SM_SQI  196608                 // 128 floats
#define SM_SQJ  (196608 + 512)         // 128 floats
#define SM_RED  (196608 + 1024)        // 256 floats
#define SMEM_TOTAL (196608 + 2048)

__device__ __nv_bfloat16 g_zb[NROWS * DIM];
__device__ float  g_sq[NROWS];
__device__ double g_accum;

// ---------------------------------------------------------------------------
// helpers
// ---------------------------------------------------------------------------
__device__ __forceinline__ uint32_t smem_u32(const void* p) {
    uint32_t a;
    asm("{ .reg .u64 t; cvta.to.shared.u64 t, %1; cvt.u32.u64 %0, t; }"
        : "=r"(a) : "l"(p));
    return a;
}

__device__ __forceinline__ void cp16(uint32_t s, const void* g) {
    asm volatile("cp.async.cg.shared.global [%0], [%1], 16;"
                 :: "r"(s), "l"(g) : "memory");
}

__device__ __forceinline__ void ldsm4(uint32_t* r, uint32_t addr) {
    asm volatile("ldmatrix.sync.aligned.m8n8.x4.shared.b16 {%0,%1,%2,%3}, [%4];"
                 : "=r"(r[0]), "=r"(r[1]), "=r"(r[2]), "=r"(r[3])
                 : "r"(addr));
}

__device__ __forceinline__ void mma16816(float* d, const uint32_t* a,
                                         const uint32_t* b) {
    asm volatile(
        "mma.sync.aligned.m16n8k16.row.col.f32.bf16.bf16.f32 "
        "{%0,%1,%2,%3}, {%4,%5,%6,%7}, {%8,%9}, {%0,%1,%2,%3};"
        : "+f"(d[0]), "+f"(d[1]), "+f"(d[2]), "+f"(d[3])
        : "r"(a[0]), "r"(a[1]), "r"(a[2]), "r"(a[3]),
          "r"(b[0]), "r"(b[1]));
}

// swizzled byte offset inside a 128x256bf16 tile; ldmatrix conflict-free.
__device__ __forceinline__ uint32_t sw_off(int row, int kc16) {
    return (uint32_t)row * 512u + (uint32_t)((kc16 ^ (row & 7)) << 4);
}

// issue the 4096 16B cp.async chunks of one 128x256 bf16 tile
__device__ __forceinline__ void load_tile(uint32_t dst,
                                          const __nv_bfloat16* src, int tid) {
    #pragma unroll
    for (int t = 0; t < 16; t++) {
        int idx = tid + t * NTHREADS;
        int row = idx >> 5;
        int kc  = idx & 31;
        cp16(dst + sw_off(row, kc), src + row * DIM + kc * 8);
    }
}

// ---------------------------------------------------------------------------
// Kernel 1: fp32 -> bf16 convert + per-row squared norms. One warp per row.
// ---------------------------------------------------------------------------
__global__ void __launch_bounds__(256) prep_kernel(const float* __restrict__ z)
{
    if (blockIdx.x == 0 && threadIdx.x == 0) g_accum = 0.0;

    const int w    = (blockIdx.x * blockDim.x + threadIdx.x) >> 5;
    const int lane = threadIdx.x & 31;
    if (w >= NROWS) return;

    const float4* row = (const float4*)(z + (size_t)w * DIM);
    float4 a = row[lane * 2];
    float4 b = row[lane * 2 + 1];

    float s = a.x*a.x + a.y*a.y + a.z*a.z + a.w*a.w
            + b.x*b.x + b.y*b.y + b.z*b.z + b.w*b.w;

    __nv_bfloat162 p0 = __floats2bfloat162_rn(a.x, a.y);
    __nv_bfloat162 p1 = __floats2bfloat162_rn(a.z, a.w);
    __nv_bfloat162 p2 = __floats2bfloat162_rn(b.x, b.y);
    __nv_bfloat162 p3 = __floats2bfloat162_rn(b.z, b.w);
    uint4 pk;
    pk.x = *(uint32_t*)&p0;  pk.y = *(uint32_t*)&p1;
    pk.z = *(uint32_t*)&p2;  pk.w = *(uint32_t*)&p3;
    *(uint4*)(g_zb + (size_t)w * DIM + lane * 8) = pk;

    #pragma unroll
    for (int o = 16; o > 0; o >>= 1)
        s += __shfl_xor_sync(0xFFFFFFFFu, s, o);
    if (lane == 0) g_sq[w] = s;
}

// ---------------------------------------------------------------------------
// Kernel 2: persistent symmetric Gram. 152 blocks, each a contiguous chunk of
// the row-major upper-triangle tile list. A reloaded on row change; B
// double-buffered and prefetched under compute.
// ---------------------------------------------------------------------------
__global__ void __launch_bounds__(NTHREADS) gram_kernel()
{
    const int p = blockIdx.x;
    const int t0  = p * TPB + (p < TREM ? p : TREM);
    const int cnt = TPB + (p < TREM ? 1 : 0);
    const int t1  = t0 + cnt;

    extern __shared__ char smem[];
    const uint32_t sb  = smem_u32(smem);
    const int tid  = threadIdx.x;
    const int wid  = tid >> 5;
    const int lane = tid & 31;

    // map t0 -> (bi, bj) in row-major upper triangle
    int bi = 0, s = 0;
    while (s + (64 - bi) <= t0) { s += 64 - bi; bi++; }
    int bj = bi + (t0 - s);

    float* sqi_s = (float*)(smem + SM_SQI);
    float* sqj_s = (float*)(smem + SM_SQJ);

    // prologue: prefetch B(t0) into buf 0
    load_tile(sb + SM_B0, g_zb + (size_t)bj * BN * DIM, tid);
    asm volatile("cp.async.commit_group;" ::: "memory");

    const int wm = (wid & 3) * 32;
    const int wn = (wid >> 2) * 64;
    const int t4 = lane >> 2;
    const int t2 = (lane & 3) << 1;

    int   loaded_bi = -1;
    int   buf = 0;
    float local = 0.0f;

    for (int t = t0; t < t1; t++) {
        // B(t) ready; all warps done with previous tile's buffers
        asm volatile("cp.async.wait_group 0;" ::: "memory");
        __syncthreads();

        const bool a_new = (bi != loaded_bi);
        if (a_new) {
            load_tile(sb + SM_A, g_zb + (size_t)bi * BM * DIM, tid);
            asm volatile("cp.async.commit_group;" ::: "memory");
            loaded_bi = bi;
            if (tid < 128) sqi_s[tid] = g_sq[bi * BM + tid];
        }
        if (tid < 128) sqj_s[tid] = g_sq[bj * BN + tid];

        // compute next tile coords; prefetch its B under this tile's compute
        int nbi = bi, nbj = bj + 1;
        if (nbj == 64) { nbi = bi + 1; nbj = nbi; }
        if (t + 1 < t1) {
            load_tile(sb + (buf ? SM_B0 : SM_B1),
                      g_zb + (size_t)nbj * BN * DIM, tid);
            asm volatile("cp.async.commit_group;" ::: "memory");
        }
        if (a_new)
            asm volatile("cp.async.wait_group 1;" ::: "memory");  // A done
        __syncthreads();

        // ---- mma over K=256 ----
        const uint32_t Bbase = sb + (buf ? SM_B1 : SM_B0);

        float acc[2][8][4];
        #pragma unroll
        for (int mi = 0; mi < 2; mi++)
            #pragma unroll
            for (int ni = 0; ni < 8; ni++)
                #pragma unroll
                for (int r = 0; r < 4; r++)
                    acc[mi][ni][r] = 0.0f;

        #pragma unroll 4
        for (int k0 = 0; k0 < DIM; k0 += 16) {
            const int kc0 = k0 >> 3;

            uint32_t a[2][4];
            #pragma unroll
            for (int mi = 0; mi < 2; mi++) {
                int row = wm + mi * 16 + (lane & 15);
                int kc  = kc0 + (lane >> 4);
                ldsm4(a[mi], sb + SM_A + sw_off(row, kc));
            }

            uint32_t b[4][4];
            #pragma unroll
            for (int nq = 0; nq < 4; nq++) {
                int row = wn + nq * 16 + (lane & 7) + ((lane >> 4) << 3);
                int kc  = kc0 + ((lane >> 3) & 1);
                ldsm4(b[nq], Bbase + sw_off(row, kc));
            }

            #pragma unroll
            for (int mi = 0; mi < 2; mi++)
                #pragma unroll
                for (int nq = 0; nq < 4; nq++) {
                    mma16816(acc[mi][nq * 2],     a[mi], &b[nq][0]);
                    mma16816(acc[mi][nq * 2 + 1], a[mi], &b[nq][2]);
                }
        }

        // ---- epilogue for this tile ----
        const bool diag = (bi == bj);
        #pragma unroll
        for (int mi = 0; mi < 2; mi++) {
            #pragma unroll
            for (int ni = 0; ni < 8; ni++) {
                #pragma unroll
                for (int r = 0; r < 4; r++) {
                    int il = wm + mi * 16 + t4 + ((r >> 1) << 3);
                    int jl = wn + ni * 8 + t2 + (r & 1);
                    float d = fmaf(-2.0f, acc[mi][ni][r],
                                   sqi_s[il] + sqj_s[jl]);
                    // off-diagonal d ~ 512 -> exp underflows to 0.0f; skip
                    if (d < 176.0f) {
                        if (!diag) {
                            local += 2.0f * __expf(-0.5f * d);
                        } else {
                            if (il == jl)      local += 1.0f;   // exact diag
                            else if (jl > il)  local += 2.0f * __expf(-0.5f * d);
                        }
                    }
                }
            }
        }

        bi = nbi; bj = nbj; buf ^= 1;
    }

    // block reduce once + one double atomic per block
    float* red = (float*)(smem + SM_RED);
    red[tid] = local;
    __syncthreads();
    #pragma unroll
    for (int s2 = NTHREADS / 2; s2 > 0; s2 >>= 1) {
        if (tid < s2) red[tid] += red[tid + s2];
        __syncthreads();
    }
    if (tid == 0 && cnt > 0) atomicAdd(&g_accum, (double)red[0]);
}

// ---------------------------------------------------------------------------
// Kernel 3: finalize (term_b / term_c underflow fp32, computed faithfully)
// ---------------------------------------------------------------------------
__global__ void finalize_kernel(float* __restrict__ out)
{
    __shared__ float fred[256];
    const int tid = threadIdx.x;

    float s = 0.0f;
    for (int idx = tid; idx < NROWS; idx += 256)
        s += __expf(-0.25f * g_sq[idx]);      // gamma/denom_b = 0.25
    fred[tid] = s;
    __syncthreads();
    #pragma unroll
    for (int t = 128; t > 0; t >>= 1) {
        if (tid < t) fred[tid] += fred[tid + t];
        __syncthreads();
    }

    if (tid == 0) {
        const double n = (double)NROWS;
        double term_a  = g_accum / (n * n);
        double coeff_b = 1.0 / pow(2.0, 128.0);   // denom_b=2, d/2=128
        double term_b  = coeff_b * ((double)fred[0] / n);
        double term_c  = 1.0 / pow(3.0, 128.0);   // (1+4*gamma)^(d/2)
        out[0] = (float)(term_a - 2.0 * term_b + term_c);
    }
}

// ---------------------------------------------------------------------------
extern "C" void kernel_launch(void* const* d_in, const int* in_sizes, int n_in,
                              void* d_out, int out_size)
{
    const float* z   = (const float*)d_in[0];
    float*       out = (float*)d_out;

    cudaFuncSetAttribute(gram_kernel,
                         cudaFuncAttributeMaxDynamicSharedMemorySize, SMEM_TOTAL);

    prep_kernel<<<NROWS / 8, 256>>>(z);

    gram_kernel<<<NBLK, NTHREADS, SMEM_TOTAL>>>();

    finalize_kernel<<<1, 256>>>(out);
}